// round 1
// baseline (speedup 1.0000x reference)
#include <cuda_runtime.h>

// Inputs (metadata order):
//   d_in[0] sample       int32  [B,3]      (head, rel, tail)
//   d_in[1] entity_emb   f32    [E,128]
//   d_in[2] relation_emb f32    [R,128]    (unused by the math)
//   d_in[3] type_emb     f32    [T*R, 128*128]
//   d_in[4] node_type    int32  [E]
// Output: f32 [B] scores.
//
// Key insight: score uses only he[0..2]; elementwise normalization means we
// only need rows 0..2 of each 128x128 matrix -> 3 dot products per sample.

#define D 128
#define TLEN 16   // T = type_emb rows / R = 3200/200

__global__ __launch_bounds__(256) void ttd_transe_kernel(
    const int*   __restrict__ sample,
    const float* __restrict__ entity_emb,
    const float* __restrict__ type_emb,
    const int*   __restrict__ node_type,
    float*       __restrict__ out,
    int B)
{
    const int gwarp = (blockIdx.x * blockDim.x + threadIdx.x) >> 5;
    const int lane  = threadIdx.x & 31;
    if (gwarp >= B) return;

    // All lanes read the same sample entries -> L1 broadcast, cheap.
    const int head = sample[gwarp * 3 + 0];
    const int rel  = sample[gwarp * 3 + 1];
    const int mrow = rel * TLEN + node_type[head];

    const float4* __restrict__ h4 =
        reinterpret_cast<const float4*>(entity_emb + (long long)head * D);
    const float4* __restrict__ m4 =
        reinterpret_cast<const float4*>(type_emb + (long long)mrow * (D * D));

    // Lane l handles floats [4l, 4l+4) of each 128-float vector.
    const float4 hv = h4[lane];
    const float4 r0 = m4[lane];          // matrix row 0
    const float4 r1 = m4[32 + lane];     // matrix row 1
    const float4 r2 = m4[64 + lane];     // matrix row 2

    float s0 = hv.x * r0.x + hv.y * r0.y + hv.z * r0.z + hv.w * r0.w;
    float s1 = hv.x * r1.x + hv.y * r1.y + hv.z * r1.z + hv.w * r1.w;
    float s2 = hv.x * r2.x + hv.y * r2.y + hv.z * r2.z + hv.w * r2.w;

    #pragma unroll
    for (int off = 16; off > 0; off >>= 1) {
        s0 += __shfl_xor_sync(0xFFFFFFFFu, s0, off);
        s1 += __shfl_xor_sync(0xFFFFFFFFu, s1, off);
        s2 += __shfl_xor_sync(0xFFFFFFFFu, s2, off);
    }

    if (lane == 0) {
        const float eps = 1e-12f;
        const float a = s0 / fmaxf(fabsf(s0), eps);
        const float b = s1 / fmaxf(fabsf(s1), eps);
        const float c = s2 / fmaxf(fabsf(s2), eps);
        out[gwarp] = fabsf(a + b - c + 1e-6f);
    }
}

extern "C" void kernel_launch(void* const* d_in, const int* in_sizes, int n_in,
                              void* d_out, int out_size)
{
    const int*   sample     = (const int*)  d_in[0];
    const float* entity_emb = (const float*)d_in[1];
    // d_in[2] relation_emb unused
    const float* type_emb   = (const float*)d_in[3];
    const int*   node_type  = (const int*)  d_in[4];
    float* out = (float*)d_out;

    const int B = out_size;                 // 8192
    const int threads = 256;                // 8 warps/block
    const int warps_per_block = threads / 32;
    const int blocks = (B + warps_per_block - 1) / warps_per_block;

    ttd_transe_kernel<<<blocks, threads>>>(sample, entity_emb, type_emb,
                                           node_type, out, B);
}